// round 1
// baseline (speedup 1.0000x reference)
#include <cuda_runtime.h>
#include <math.h>

#define BATCH 128
#define N 256
#define NP1 (N + 1)
#define NUM_CLASSES 8
#define CE_COEFF 10.0f

// Per-batch loss scratch (no device allocation allowed).
__device__ float g_batch_loss[BATCH];

// One CTA per batch. 256 threads; thread tid owns column j = tid+1 (1-based).
// Exact Jonker-Volgenant / Hungarian identical in logic to the numpy reference:
// sequential augmenting rows, parallel column scan + argmin per Dijkstra step.
__global__ __launch_bounds__(N, 1) void hungarian_loss_kernel(
    const float* __restrict__ set1,   // [B, N, 3]
    const float* __restrict__ set2)   // [B, N, 10]
{
    const int b   = blockIdx.x;
    const int tid = threadIdx.x;
    const int j   = tid + 1;          // 1-based column id

    __shared__ float s1x[N], s1y[N], s1l[N];
    __shared__ float s2x[N], s2y[N];
    __shared__ float u[NP1];          // row duals (indexed by row id 0..N)
    __shared__ int   p[NP1];          // p[j] = row (1-based) matched to column j; p[0] = current row
    __shared__ int   way[NP1];        // predecessor column on shortest path
    __shared__ float wval[8];
    __shared__ int   widx[8];
    __shared__ float sdelta;
    __shared__ int   sj1;
    __shared__ float swsum[8];

    const float* s1p = set1 + (size_t)b * N * 3;
    const float* s2p = set2 + (size_t)b * N * 10;

    s1x[tid] = s1p[tid * 3 + 0];
    s1y[tid] = s1p[tid * 3 + 1];
    s1l[tid] = s1p[tid * 3 + 2];
    s2x[tid] = s2p[tid * 10 + 0];
    s2y[tid] = s2p[tid * 10 + 1];
    u[tid]   = 0.0f;
    p[tid]   = 0;
    way[tid] = 0;
    if (tid == 0) { u[N] = 0.0f; p[N] = 0; way[N] = 0; }
    __syncthreads();

    // Thread-private column state (column = tid, 0-based for coords).
    const float c2x = s2x[tid];
    const float c2y = s2y[tid];
    float my_v = 0.0f;                // column dual v[j]

    for (int i = 1; i <= N; ++i) {
        if (tid == 0) p[0] = i;
        float my_minv = 1e18f;
        bool  my_used = false;
        int   j0 = 0;
        __syncthreads();              // p[0] + previous-row p updates visible

        while (true) {
            const int   i0 = p[j0];   // stable during Dijkstra
            const float u0 = u[i0];
            if (j == j0) my_used = true;

            float cand = 1e18f;
            if (!my_used) {
                const float dx = s1x[i0 - 1] - c2x;
                const float dy = s1y[i0 - 1] - c2y;
                const float cost = sqrtf(fmaxf(dx * dx + dy * dy, 0.0f));
                const float cur = cost - u0 - my_v;
                if (cur < my_minv) { my_minv = cur; way[j] = j0; }
                cand = my_minv;
            }

            // Block argmin over (cand, j), ties -> smallest j (numpy argmin order).
            float rv = cand; int ri = j;
            #pragma unroll
            for (int off = 16; off > 0; off >>= 1) {
                const float ov = __shfl_down_sync(0xffffffffu, rv, off);
                const int   oi = __shfl_down_sync(0xffffffffu, ri, off);
                if (ov < rv || (ov == rv && oi < ri)) { rv = ov; ri = oi; }
            }
            if ((tid & 31) == 0) { wval[tid >> 5] = rv; widx[tid >> 5] = ri; }
            __syncthreads();
            if (tid == 0) {
                float bv = wval[0]; int bi = widx[0];
                #pragma unroll
                for (int w = 1; w < 8; ++w) {
                    const float ov = wval[w]; const int oi = widx[w];
                    if (ov < bv || (ov == bv && oi < bi)) { bv = ov; bi = oi; }
                }
                sdelta = bv; sj1 = bi;
            }
            __syncthreads();
            const float delta = sdelta;
            const int   j1    = sj1;

            if (my_used) {
                my_v -= delta;
                u[p[j]] += delta;     // distinct rows across used columns -> race-free
            } else {
                my_minv -= delta;
            }
            if (tid == 0) u[p[0]] += delta;  // the "used[0]" entry (current row i)

            j0 = j1;
            const bool done = (p[j1] == 0);
            __syncthreads();          // u/way writes visible before next scan / augment
            if (done) break;
        }

        // Augment along way[] chain (serial, thread 0).
        if (tid == 0) {
            int jj = j0;
            while (jj != 0) {
                const int jp = way[jj];
                p[jj] = p[jp];
                jj = jp;
            }
        }
        // visibility handled by loop-top __syncthreads (or the one below after the loop)
    }
    __syncthreads();

    // ---- Loss epilogue. Thread tid owns column c = tid, matched row r = p[j]-1. ----
    const int r = p[j] - 1;

    // matched distance
    const float dx = s1x[r] - c2x;
    const float dy = s1y[r] - c2y;
    const float md = sqrtf(fmaxf(dx * dx + dy * dy, 0.0f));

    // cross-entropy: logits = set2[b, c, 2:10], target = (int)set1[b, r, 2]
    float lg[NUM_CLASSES];
    float mx = -1e30f;
    #pragma unroll
    for (int k = 0; k < NUM_CLASSES; ++k) {
        lg[k] = s2p[tid * 10 + 2 + k];
        mx = fmaxf(mx, lg[k]);
    }
    float se = 0.0f;
    #pragma unroll
    for (int k = 0; k < NUM_CLASSES; ++k) se += expf(lg[k] - mx);
    const float lse = mx + logf(se);

    const int  t    = (int)s1l[r];
    const bool mask = (t != -1);
    const int  st   = mask ? ((t < 0) ? 0 : (t >= NUM_CLASSES ? NUM_CLASSES - 1 : t)) : 0;
    const float nll = mask ? (lse - lg[st]) : 0.0f;
    const float cnt = mask ? 1.0f : 0.0f;

    // Block sums: matched dist, nll, mask count.
    float sv[3] = { md, nll, cnt };
    #pragma unroll
    for (int q = 0; q < 3; ++q) {
        float v = sv[q];
        #pragma unroll
        for (int off = 16; off > 0; off >>= 1)
            v += __shfl_down_sync(0xffffffffu, v, off);
        if ((tid & 31) == 0) swsum[tid >> 5] = v;
        __syncthreads();
        if (tid == 0) {
            float s = 0.0f;
            #pragma unroll
            for (int w = 0; w < 8; ++w) s += swsum[w];
            sv[q] = s;
        }
        __syncthreads();
    }

    if (tid == 0) {
        const float loss1 = sv[0] / (float)N;
        const float denom = fmaxf(sv[2], 1.0f);
        const float loss2 = CE_COEFF * (sv[1] / denom);
        g_batch_loss[b] = loss1 + loss2;
    }
}

__global__ void finalize_kernel(float* __restrict__ out) {
    __shared__ float s[BATCH];
    const int t = threadIdx.x;
    s[t] = g_batch_loss[t];
    __syncthreads();
    #pragma unroll
    for (int off = BATCH / 2; off > 0; off >>= 1) {
        if (t < off) s[t] += s[t + off];
        __syncthreads();
    }
    if (t == 0) out[0] = s[0];
}

extern "C" void kernel_launch(void* const* d_in, const int* in_sizes, int n_in,
                              void* d_out, int out_size) {
    (void)in_sizes; (void)n_in; (void)out_size;
    const float* set1 = (const float*)d_in[0];
    const float* set2 = (const float*)d_in[1];
    float* out = (float*)d_out;

    hungarian_loss_kernel<<<BATCH, N>>>(set1, set2);
    finalize_kernel<<<1, BATCH>>>(out);
}